// round 3
// baseline (speedup 1.0000x reference)
#include <cuda_runtime.h>
#include <cstdint>

#define NN 16384
#define HH 2048
#define KN 25
#define CHUNK 128
#define NCHUNK (HH / CHUNK)
#define RPW 4
#define NWARPS 4
#define RPB (RPW * NWARPS)         // 16 rows per block
#define NTHREADS (NWARPS * 32)     // 128
#define STAGES 3
#define CHUNK_BYTES (KN * CHUNK * 4)   // 12800
#define KP 12                      // 12 k-pairs + 1 leftover k

typedef unsigned long long ull;

__device__ __forceinline__ uint32_t smem_u32(const void* p) {
    return (uint32_t)__cvta_generic_to_shared(p);
}
__device__ __forceinline__ void bulk_g2s(uint32_t dst, const void* src,
                                         uint32_t bytes, uint32_t mbar) {
    asm volatile(
        "cp.async.bulk.shared::cta.global.mbarrier::complete_tx::bytes [%0], [%1], %2, [%3];"
        :: "r"(dst), "l"(src), "r"(bytes), "r"(mbar) : "memory");
}
__device__ __forceinline__ void mbar_init(uint32_t mbar, uint32_t count) {
    asm volatile("mbarrier.init.shared.b64 [%0], %1;" :: "r"(mbar), "r"(count) : "memory");
}
__device__ __forceinline__ void mbar_expect_tx(uint32_t mbar, uint32_t bytes) {
    asm volatile("mbarrier.arrive.expect_tx.shared.b64 _, [%0], %1;"
                 :: "r"(mbar), "r"(bytes) : "memory");
}
__device__ __forceinline__ void mbar_wait(uint32_t mbar, uint32_t parity) {
    asm volatile(
        "{\n\t.reg .pred P1;\n\t"
        "WAIT_LOOP_%=:\n\t"
        "mbarrier.try_wait.parity.acquire.cta.shared::cta.b64 P1, [%0], %1, 0x989680;\n\t"
        "@P1 bra.uni WAIT_DONE_%=;\n\t"
        "bra.uni WAIT_LOOP_%=;\n\t"
        "WAIT_DONE_%=:\n\t}"
        :: "r"(mbar), "r"(parity) : "memory");
}

__device__ __forceinline__ ull ffma2(ull a, ull b, ull c) {
    ull d;
    asm("fma.rn.f32x2 %0, %1, %2, %3;" : "=l"(d) : "l"(a), "l"(b), "l"(c));
    return d;
}
__device__ __forceinline__ ull pack2(float lo, float hi) {
    ull r;
    asm("mov.b64 %0, {%1, %2};" : "=l"(r) : "f"(lo), "f"(hi));
    return r;
}
__device__ __forceinline__ void unpack2(ull v, float& lo, float& hi) {
    asm("mov.b64 {%0, %1}, %2;" : "=f"(lo), "=f"(hi) : "l"(v));
}

__global__ __launch_bounds__(NTHREADS, 2)
void nce_kernel(const float* __restrict__ input,
                const float* __restrict__ weight,
                const float* __restrict__ bias,
                const float* __restrict__ unig,
                const int* __restrict__ target,
                const int* __restrict__ noise,
                float* __restrict__ out)
{
    __shared__ __align__(1024) float sw[STAGES][KN][CHUNK];  // 38.4 KB ring
    __shared__ __align__(8) ull mbar_store[STAGES];
    __shared__ int s_noise[KN];
    __shared__ float s_nb[KN], s_nu[KN];

    const int tid  = threadIdx.x;
    const int lane = tid & 31;
    const int wid  = tid >> 5;
    const int rb   = blockIdx.x * RPB;
    const int row0 = rb + wid * RPW;

    const uint32_t mb_base = smem_u32(&mbar_store[0]);
    const uint32_t sw_base = smem_u32(&sw[0][0][0]);

    if (tid < KN) {
        int nk = noise[tid];
        s_noise[tid] = nk;
        s_nb[tid] = bias[nk];
        s_nu[tid] = unig[nk];
    }
    if (tid == 0) {
        mbar_init(mb_base + 0,  1);
        mbar_init(mb_base + 8,  1);
        mbar_init(mb_base + 16, 1);
    }
    asm volatile("fence.proxy.async.shared::cta;" ::: "memory");
    __syncthreads();

    // ---- prolog: fill stages 0 and 1 of the noise-tile ring ----
    if (tid == 0) {
        #pragma unroll 1
        for (int st = 0; st < 2; st++) {
            mbar_expect_tx(mb_base + st * 8, CHUNK_BYTES);
            #pragma unroll 1
            for (int k = 0; k < KN; k++) {
                const float* g = weight + (size_t)s_noise[k] * HH + st * CHUNK;
                bulk_g2s(sw_base + (uint32_t)(st * KN * CHUNK + k * CHUNK) * 4u,
                         g, CHUNK * 4, mb_base + st * 8);
            }
        }
    }

    // ---- early independent outputs: pnn (broadcast) and pnt ----
    {
        const size_t pnn_base = (size_t)2 * NN + (size_t)NN * KN + (size_t)rb * KN;
        #pragma unroll 1
        for (int i = tid; i < RPB * KN; i += NTHREADS)
            out[pnn_base + i] = s_nu[i % KN];
        if (tid < RPB) {
            int n = rb + tid;
            out[NN + n] = unig[target[n]];
        }
    }

    int tgt[RPW];
    const float4* xp[RPW];
    const float4* wtp[RPW];
    #pragma unroll
    for (int r = 0; r < RPW; r++) {
        int n = row0 + r;
        tgt[r] = target[n];
        xp[r]  = reinterpret_cast<const float4*>(input)  + (size_t)n * (HH / 4);
        wtp[r] = reinterpret_cast<const float4*>(weight) + (size_t)tgt[r] * (HH / 4);
    }

    ull acc2[RPW][KP];           // (k=2j, k=2j+1) packed partials
    float accl[RPW];             // k = 24
    float acct[RPW];             // target
    #pragma unroll
    for (int r = 0; r < RPW; r++) {
        accl[r] = 0.f; acct[r] = 0.f;
        #pragma unroll
        for (int j = 0; j < KP; j++) acc2[r][j] = pack2(0.f, 0.f);
    }

    // chunk-0 x / target-weight
    float4 x4[RPW], wt4[RPW];
    #pragma unroll
    for (int r = 0; r < RPW; r++) { x4[r] = xp[r][lane]; wt4[r] = wtp[r][lane]; }

    #pragma unroll 1
    for (int c = 0; c < NCHUNK; c++) {
        const int s = c % STAGES;

        // producer: refill stage (c+2)%3 for chunk c+2 (freed at end of c-1)
        if (tid == 0 && c + 2 < NCHUNK) {
            const int s2 = (c + 2) % STAGES;
            mbar_expect_tx(mb_base + s2 * 8, CHUNK_BYTES);
            #pragma unroll 1
            for (int k = 0; k < KN; k++) {
                const float* g = weight + (size_t)s_noise[k] * HH + (c + 2) * CHUNK;
                bulk_g2s(sw_base + (uint32_t)(s2 * KN * CHUNK + k * CHUNK) * 4u,
                         g, CHUNK * 4, mb_base + s2 * 8);
            }
        }

        // prefetch next chunk's x / wt before waiting (long latency cover)
        const int cn = (c + 1 < NCHUNK) ? c + 1 : c;
        float4 x4n[RPW], wt4n[RPW];
        #pragma unroll
        for (int r = 0; r < RPW; r++) {
            x4n[r]  = xp[r][cn * (CHUNK / 4) + lane];
            wt4n[r] = wtp[r][cn * (CHUNK / 4) + lane];
        }

        mbar_wait(mb_base + s * 8, (c / STAGES) & 1);

        // x broadcast pairs (same value in both halves)
        ull xb[RPW][4];
        #pragma unroll
        for (int r = 0; r < RPW; r++) {
            xb[r][0] = pack2(x4[r].x, x4[r].x);
            xb[r][1] = pack2(x4[r].y, x4[r].y);
            xb[r][2] = pack2(x4[r].z, x4[r].z);
            xb[r][3] = pack2(x4[r].w, x4[r].w);
        }

        const float4* wbase = reinterpret_cast<const float4*>(&sw[s][0][0]) + lane;
        #pragma unroll
        for (int j = 0; j < KP; j++) {
            float4 wa = wbase[(2 * j)     * (CHUNK / 4)];
            float4 wb = wbase[(2 * j + 1) * (CHUNK / 4)];
            ull w0 = pack2(wa.x, wb.x);
            ull w1 = pack2(wa.y, wb.y);
            ull w2 = pack2(wa.z, wb.z);
            ull w3 = pack2(wa.w, wb.w);
            #pragma unroll
            for (int r = 0; r < RPW; r++) {
                ull a = acc2[r][j];
                a = ffma2(xb[r][0], w0, a);
                a = ffma2(xb[r][1], w1, a);
                a = ffma2(xb[r][2], w2, a);
                a = ffma2(xb[r][3], w3, a);
                acc2[r][j] = a;
            }
        }
        {   // leftover k = 24 (scalar)
            float4 wl = wbase[24 * (CHUNK / 4)];
            #pragma unroll
            for (int r = 0; r < RPW; r++) {
                float a = accl[r];
                a = fmaf(x4[r].x, wl.x, a);
                a = fmaf(x4[r].y, wl.y, a);
                a = fmaf(x4[r].z, wl.z, a);
                a = fmaf(x4[r].w, wl.w, a);
                accl[r] = a;
            }
        }
        #pragma unroll
        for (int r = 0; r < RPW; r++) {   // target row (scalar)
            float a = acct[r];
            a = fmaf(x4[r].x, wt4[r].x, a);
            a = fmaf(x4[r].y, wt4[r].y, a);
            a = fmaf(x4[r].z, wt4[r].z, a);
            a = fmaf(x4[r].w, wt4[r].w, a);
            acct[r] = a;
        }

        #pragma unroll
        for (int r = 0; r < RPW; r++) { x4[r] = x4n[r]; wt4[r] = wt4n[r]; }

        __syncthreads();   // all warps done with stage s before it refills
    }

    // ---- reduce + store outputs ----
    #pragma unroll
    for (int r = 0; r < RPW; r++) {
        float v[KN];
        #pragma unroll
        for (int j = 0; j < KP; j++) unpack2(acc2[r][j], v[2 * j], v[2 * j + 1]);
        v[24] = accl[r];
        float t = acct[r];

        #pragma unroll
        for (int off = 16; off > 0; off >>= 1) {
            t += __shfl_xor_sync(0xffffffffu, t, off);
            #pragma unroll
            for (int k = 0; k < KN; k++)
                v[k] += __shfl_xor_sync(0xffffffffu, v[k], off);
        }

        const int n = row0 + r;
        float* pmn_row = out + (size_t)2 * NN + (size_t)n * KN;
        #pragma unroll
        for (int k = 0; k < KN; k++) {
            if (lane == k) pmn_row[k] = expf(v[k] + s_nb[k]);
        }
        if (lane == KN) {
            out[n] = expf(t + bias[tgt[r]]);
        }
    }
}

extern "C" void kernel_launch(void* const* d_in, const int* in_sizes, int n_in,
                              void* d_out, int out_size) {
    const float* input  = (const float*)d_in[0];
    const float* weight = (const float*)d_in[1];
    const float* bias   = (const float*)d_in[2];
    const float* unig   = (const float*)d_in[3];
    const int*   target = (const int*)d_in[4];
    const int*   noise  = (const int*)d_in[5];
    float* out = (float*)d_out;

    nce_kernel<<<NN / RPB, NTHREADS>>>(input, weight, bias, unig, target, noise, out);
}

// round 4
// speedup vs baseline: 1.5953x; 1.5953x over previous
#include <cuda_runtime.h>
#include <cstdint>

#define NN 16384
#define HH 2048
#define KN 25
#define CHUNK 128
#define NCHUNK (HH / CHUNK)        // 16
#define RPW 4
#define NWARPS 8
#define NTHREADS (NWARPS * 32)     // 256
#define GROUPS 4
#define RPB (NWARPS * RPW * GROUPS)  // 128 rows per block
#define SMEM_BYTES (KN * HH * 4)     // 204800

__global__ __launch_bounds__(NTHREADS, 1)
void nce_kernel(const float* __restrict__ input,
                const float* __restrict__ weight,
                const float* __restrict__ bias,
                const float* __restrict__ unig,
                const int* __restrict__ target,
                const int* __restrict__ noise,
                float* __restrict__ out)
{
    extern __shared__ __align__(16) float sw[];   // [KN][HH] full noise-weight tile
    __shared__ int s_noise[KN];
    __shared__ float s_nb[KN], s_nu[KN];

    const int tid  = threadIdx.x;
    const int lane = tid & 31;
    const int wid  = tid >> 5;
    const int rb   = blockIdx.x * RPB;

    if (tid < KN) {
        int nk = noise[tid];
        s_noise[tid] = nk;
        s_nb[tid] = bias[nk];
        s_nu[tid] = unig[nk];
    }
    __syncthreads();

    // ---- early independent outputs: pnn (broadcast) and pnt (gathered unigram) ----
    {
        const size_t pnn_base = (size_t)2 * NN + (size_t)NN * KN + (size_t)rb * KN;
        #pragma unroll 1
        for (int i = tid; i < RPB * KN; i += NTHREADS)
            out[pnn_base + i] = s_nu[i % KN];
        #pragma unroll 1
        for (int i = tid; i < RPB; i += NTHREADS) {
            int n = rb + i;
            out[NN + n] = unig[target[n]];
        }
    }

    // ---- fill the whole 25 x 2048 noise tile into smem (coalesced, once) ----
    {
        const float4* w4 = reinterpret_cast<const float4*>(weight);
        float4* s4 = reinterpret_cast<float4*>(sw);
        #pragma unroll 1
        for (int idx = tid; idx < KN * (HH / 4); idx += NTHREADS) {
            int k = idx / (HH / 4);
            int j = idx - k * (HH / 4);
            s4[idx] = w4[(size_t)s_noise[k] * (HH / 4) + j];
        }
    }
    __syncthreads();
    // ======== from here on: NO synchronization; warps free-run ========

    #pragma unroll 1
    for (int g = 0; g < GROUPS; g++) {
        const int row0 = rb + (wid * GROUPS + g) * RPW;

        int tgt[RPW];
        const float4* xp[RPW];
        const float4* wtp[RPW];
        #pragma unroll
        for (int r = 0; r < RPW; r++) {
            int n = row0 + r;
            tgt[r] = target[n];
            xp[r]  = reinterpret_cast<const float4*>(input)  + (size_t)n * (HH / 4);
            wtp[r] = reinterpret_cast<const float4*>(weight) + (size_t)tgt[r] * (HH / 4);
        }

        float acc[RPW][KN];
        float acct[RPW];
        #pragma unroll
        for (int r = 0; r < RPW; r++) {
            acct[r] = 0.f;
            #pragma unroll
            for (int k = 0; k < KN; k++) acc[r][k] = 0.f;
        }

        // chunk-0 register prefetch
        float4 x4[RPW], wt4[RPW];
        #pragma unroll
        for (int r = 0; r < RPW; r++) { x4[r] = xp[r][lane]; wt4[r] = wtp[r][lane]; }

        #pragma unroll 1
        for (int c = 0; c < NCHUNK; c++) {
            // prefetch next chunk's x / target-w (covers DRAM latency under compute)
            float4 x4n[RPW], wt4n[RPW];
            const int cn = (c + 1 < NCHUNK) ? c + 1 : c;
            #pragma unroll
            for (int r = 0; r < RPW; r++) {
                x4n[r]  = xp[r][cn * (CHUNK / 4) + lane];
                wt4n[r] = wtp[r][cn * (CHUNK / 4) + lane];
            }

            // noise-row dot products from smem (conflict-free LDS.128)
            const float4* wrow = reinterpret_cast<const float4*>(sw)
                                 + c * (CHUNK / 4) + lane;
            #pragma unroll
            for (int k = 0; k < KN; k++) {
                float4 w = wrow[k * (HH / 4)];
                #pragma unroll
                for (int r = 0; r < RPW; r++) {
                    float a = acc[r][k];
                    a = fmaf(x4[r].x, w.x, a);
                    a = fmaf(x4[r].y, w.y, a);
                    a = fmaf(x4[r].z, w.z, a);
                    a = fmaf(x4[r].w, w.w, a);
                    acc[r][k] = a;
                }
            }
            // target-row dot products
            #pragma unroll
            for (int r = 0; r < RPW; r++) {
                float a = acct[r];
                a = fmaf(x4[r].x, wt4[r].x, a);
                a = fmaf(x4[r].y, wt4[r].y, a);
                a = fmaf(x4[r].z, wt4[r].z, a);
                a = fmaf(x4[r].w, wt4[r].w, a);
                acct[r] = a;
            }

            #pragma unroll
            for (int r = 0; r < RPW; r++) { x4[r] = x4n[r]; wt4[r] = wt4n[r]; }
        }

        // ---- warp butterfly reduction over lanes ----
        #pragma unroll
        for (int off = 16; off > 0; off >>= 1) {
            #pragma unroll
            for (int r = 0; r < RPW; r++) {
                acct[r] += __shfl_xor_sync(0xffffffffu, acct[r], off);
                #pragma unroll
                for (int k = 0; k < KN; k++)
                    acc[r][k] += __shfl_xor_sync(0xffffffffu, acc[r][k], off);
            }
        }

        // ---- outputs: pmn via predicated constant-index stores, pmt ----
        #pragma unroll
        for (int r = 0; r < RPW; r++) {
            const int n = row0 + r;
            float* pmn_row = out + (size_t)2 * NN + (size_t)n * KN;
            #pragma unroll
            for (int k = 0; k < KN; k++) {
                if (lane == k) pmn_row[k] = expf(acc[r][k] + s_nb[k]);
            }
            if (lane == KN) {
                out[n] = expf(acct[r] + bias[tgt[r]]);
            }
        }
    }
}

extern "C" void kernel_launch(void* const* d_in, const int* in_sizes, int n_in,
                              void* d_out, int out_size) {
    const float* input  = (const float*)d_in[0];
    const float* weight = (const float*)d_in[1];
    const float* bias   = (const float*)d_in[2];
    const float* unig   = (const float*)d_in[3];
    const int*   target = (const int*)d_in[4];
    const int*   noise  = (const int*)d_in[5];
    float* out = (float*)d_out;

    cudaFuncSetAttribute(nce_kernel,
                         cudaFuncAttributeMaxDynamicSharedMemorySize, SMEM_BYTES);
    nce_kernel<<<NN / RPB, NTHREADS, SMEM_BYTES>>>(input, weight, bias, unig,
                                                   target, noise, out);
}

// round 5
// speedup vs baseline: 1.7778x; 1.1144x over previous
#include <cuda_runtime.h>
#include <cstdint>

#define NN 16384
#define HH 2048
#define H4 (HH / 4)            // 512 float4 per row
#define KN 25
#define CHUNK 128
#define C4 (CHUNK / 4)         // 32
#define NCHUNK (HH / CHUNK)    // 16
#define RPW 4
#define NWARPS 8
#define NTHREADS 256
#define G 2
#define RPB (NWARPS * RPW * G) // 64 rows per block
#define NROWBLK (NN / RPB)     // 256
#define SMEM_BYTES (13 * HH * 4)   // 106496

// NC = number of smem noise columns this half owns; HT = also compute target dot
template <int NC, bool HT>
__device__ __forceinline__ void run_half(
    const float* __restrict__ input, const float* __restrict__ weight,
    const float* __restrict__ bias, const int* __restrict__ target,
    const float* __restrict__ sw, const float* __restrict__ s_nb,
    float* __restrict__ out, int rb, int wid, int lane, int kbase)
{
    const float4* xg = reinterpret_cast<const float4*>(input);
    const float4* wg = reinterpret_cast<const float4*>(weight);

    #pragma unroll 1
    for (int g = 0; g < G; g++) {
        const int row0 = rb + (wid * G + g) * RPW;

        int tgt[RPW];
        if (HT) {
            #pragma unroll
            for (int r = 0; r < RPW; r++) tgt[r] = target[row0 + r];
        }

        float acc[RPW][NC];
        float acct[RPW];
        #pragma unroll
        for (int r = 0; r < RPW; r++) {
            acct[r] = 0.f;
            #pragma unroll
            for (int j = 0; j < NC; j++) acc[r][j] = 0.f;
        }

        float4 x4[RPW];
        #pragma unroll
        for (int r = 0; r < RPW; r++)
            x4[r] = xg[(size_t)(row0 + r) * H4 + lane];

        #pragma unroll 1
        for (int c = 0; c < NCHUNK; c++) {
            // prefetch next chunk's x
            const int cn = (c + 1 < NCHUNK) ? c + 1 : c;
            float4 x4n[RPW];
            #pragma unroll
            for (int r = 0; r < RPW; r++)
                x4n[r] = xg[(size_t)(row0 + r) * H4 + cn * C4 + lane];

            // target-row weights for THIS chunk: issued now, consumed after
            // the 12/13 smem columns (~500 cycles of FFMA) -> latency covered
            float4 wt4[RPW];
            if (HT) {
                #pragma unroll
                for (int r = 0; r < RPW; r++)
                    wt4[r] = wg[(size_t)tgt[r] * H4 + c * C4 + lane];
            }

            const float4* wrow = reinterpret_cast<const float4*>(sw) + c * C4 + lane;
            #pragma unroll
            for (int j = 0; j < NC; j++) {
                float4 w = wrow[j * H4];
                #pragma unroll
                for (int r = 0; r < RPW; r++) {
                    float a = acc[r][j];
                    a = fmaf(x4[r].x, w.x, a);
                    a = fmaf(x4[r].y, w.y, a);
                    a = fmaf(x4[r].z, w.z, a);
                    a = fmaf(x4[r].w, w.w, a);
                    acc[r][j] = a;
                }
            }
            if (HT) {
                #pragma unroll
                for (int r = 0; r < RPW; r++) {
                    float a = acct[r];
                    a = fmaf(x4[r].x, wt4[r].x, a);
                    a = fmaf(x4[r].y, wt4[r].y, a);
                    a = fmaf(x4[r].z, wt4[r].z, a);
                    a = fmaf(x4[r].w, wt4[r].w, a);
                    acct[r] = a;
                }
            }
            #pragma unroll
            for (int r = 0; r < RPW; r++) x4[r] = x4n[r];
        }

        // warp butterfly reduction over lanes (disjoint H slices)
        #pragma unroll
        for (int off = 16; off > 0; off >>= 1) {
            #pragma unroll
            for (int r = 0; r < RPW; r++) {
                if (HT) acct[r] += __shfl_xor_sync(0xffffffffu, acct[r], off);
                #pragma unroll
                for (int j = 0; j < NC; j++)
                    acc[r][j] += __shfl_xor_sync(0xffffffffu, acc[r][j], off);
            }
        }

        // outputs
        #pragma unroll
        for (int r = 0; r < RPW; r++) {
            const int n = row0 + r;
            float* pmn_row = out + (size_t)2 * NN + (size_t)n * KN + kbase;
            #pragma unroll
            for (int j = 0; j < NC; j++) {
                if (lane == j) pmn_row[j] = expf(acc[r][j] + s_nb[j]);
            }
            if (HT && lane == NC) {
                out[n] = expf(acct[r] + bias[tgt[r]]);
            }
        }
    }
}

__global__ __launch_bounds__(NTHREADS, 2)
void nce_kernel(const float* __restrict__ input,
                const float* __restrict__ weight,
                const float* __restrict__ bias,
                const float* __restrict__ unig,
                const int* __restrict__ target,
                const int* __restrict__ noise,
                float* __restrict__ out)
{
    extern __shared__ __align__(16) float sw[];   // up to 13 x 2048 noise rows
    __shared__ float s_nb[13];
    __shared__ float s_nu[KN];
    __shared__ int   s_nk[13];

    const int tid   = threadIdx.x;
    const int lane  = tid & 31;
    const int wid   = tid >> 5;
    const int bid   = blockIdx.x;
    const int khalf = bid & 1;            // 0: noise 0..11 + target; 1: noise 12..24
    const int rb    = (bid >> 1) * RPB;
    const int kbase = khalf ? 12 : 0;
    const int nc    = khalf ? 13 : 12;

    if (tid < nc) {
        int nk = noise[kbase + tid];
        s_nk[tid] = nk;
        s_nb[tid] = bias[nk];
    }
    if (khalf == 0 && tid < KN) s_nu[tid] = unig[noise[tid]];
    __syncthreads();

    // ---- early independent outputs (khalf 0 only): pnn + pnt ----
    if (khalf == 0) {
        const size_t pnn_base = (size_t)2 * NN + (size_t)NN * KN + (size_t)rb * KN;
        #pragma unroll 1
        for (int i = tid; i < RPB * KN; i += NTHREADS)
            out[pnn_base + i] = s_nu[i % KN];
        if (tid < RPB) {
            int n = rb + tid;
            out[NN + n] = unig[target[n]];
        }
    }

    // ---- fill this half's noise tile into smem (coalesced, once) ----
    {
        const float4* w4 = reinterpret_cast<const float4*>(weight);
        float4* s4 = reinterpret_cast<float4*>(sw);
        const int total = nc * H4;
        #pragma unroll 1
        for (int idx = tid; idx < total; idx += NTHREADS) {
            int j = idx >> 9;          // / H4
            int h = idx & (H4 - 1);
            s4[idx] = w4[(size_t)s_nk[j] * H4 + h];
        }
    }
    __syncthreads();
    // ======== free-running from here ========

    if (khalf == 0)
        run_half<12, true >(input, weight, bias, target, sw, s_nb, out, rb, wid, lane, 0);
    else
        run_half<13, false>(input, weight, bias, target, sw, s_nb, out, rb, wid, lane, 12);
}

extern "C" void kernel_launch(void* const* d_in, const int* in_sizes, int n_in,
                              void* d_out, int out_size) {
    const float* input  = (const float*)d_in[0];
    const float* weight = (const float*)d_in[1];
    const float* bias   = (const float*)d_in[2];
    const float* unig   = (const float*)d_in[3];
    const int*   target = (const int*)d_in[4];
    const int*   noise  = (const int*)d_in[5];
    float* out = (float*)d_out;

    cudaFuncSetAttribute(nce_kernel,
                         cudaFuncAttributeMaxDynamicSharedMemorySize, SMEM_BYTES);
    nce_kernel<<<NROWBLK * 2, NTHREADS, SMEM_BYTES>>>(input, weight, bias, unig,
                                                      target, noise, out);
}

// round 7
// speedup vs baseline: 1.9831x; 1.1154x over previous
#include <cuda_runtime.h>
#include <cstdint>

#define NN 16384
#define HH 2048
#define H4 (HH / 4)            // 512 float4 per row
#define KN 25
#define CHUNK 128
#define C4 (CHUNK / 4)         // 32
#define NCHUNK (HH / CHUNK)    // 16
#define RPW 4
#define NWARPS 8
#define NTHREADS 256
#define G 2
#define RPB (NWARPS * RPW * G) // 64 rows per block
#define NROWBLK (NN / RPB)     // 256
#define NQ 4
#define MAXNC 7
#define SMEM_BYTES (MAXNC * HH * 4)   // 57344

__constant__ int c_kbase[NQ] = {0, 7, 14, 20};
__constant__ int c_kcnt[NQ]  = {7, 7, 6, 5};   // quarter 3 also owns the target dot

// NC = noise cols this quarter owns; HT = also compute target dot
template <int NC, bool HT>
__device__ __forceinline__ void run_quarter(
    const float* __restrict__ input, const float* __restrict__ weight,
    const float* __restrict__ bias, const int* __restrict__ target,
    const float* __restrict__ sw, const float* __restrict__ s_nb,
    float* __restrict__ out, int rb, int wid, int lane, int kbase)
{
    const float4* xg = reinterpret_cast<const float4*>(input);
    const float4* wg = reinterpret_cast<const float4*>(weight);

    #pragma unroll 1
    for (int g = 0; g < G; g++) {
        const int row0 = rb + (wid * G + g) * RPW;

        int tgt[RPW];
        if (HT) {
            #pragma unroll
            for (int r = 0; r < RPW; r++) tgt[r] = target[row0 + r];
        }

        float acc[RPW][NC];
        float acct[RPW];
        #pragma unroll
        for (int r = 0; r < RPW; r++) {
            acct[r] = 0.f;
            #pragma unroll
            for (int j = 0; j < NC; j++) acc[r][j] = 0.f;
        }

        float4 x4[RPW];
        #pragma unroll
        for (int r = 0; r < RPW; r++)
            x4[r] = xg[(size_t)(row0 + r) * H4 + lane];

        #pragma unroll 1
        for (int c = 0; c < NCHUNK; c++) {
            // prefetch next chunk's x (consumed next iteration)
            const int cn = (c + 1 < NCHUNK) ? c + 1 : c;
            float4 x4n[RPW];
            #pragma unroll
            for (int r = 0; r < RPW; r++)
                x4n[r] = xg[(size_t)(row0 + r) * H4 + cn * C4 + lane];

            // target-row weights for THIS chunk: issued now, consumed after
            // the NC smem columns of FFMA -> latency covered
            float4 wt4[RPW];
            if (HT) {
                #pragma unroll
                for (int r = 0; r < RPW; r++)
                    wt4[r] = wg[(size_t)tgt[r] * H4 + c * C4 + lane];
            }

            const float4* wrow = reinterpret_cast<const float4*>(sw) + c * C4 + lane;
            #pragma unroll
            for (int j = 0; j < NC; j++) {
                float4 w = wrow[j * H4];
                #pragma unroll
                for (int r = 0; r < RPW; r++) {
                    float a = acc[r][j];
                    a = fmaf(x4[r].x, w.x, a);
                    a = fmaf(x4[r].y, w.y, a);
                    a = fmaf(x4[r].z, w.z, a);
                    a = fmaf(x4[r].w, w.w, a);
                    acc[r][j] = a;
                }
            }
            if (HT) {
                #pragma unroll
                for (int r = 0; r < RPW; r++) {
                    float a = acct[r];
                    a = fmaf(x4[r].x, wt4[r].x, a);
                    a = fmaf(x4[r].y, wt4[r].y, a);
                    a = fmaf(x4[r].z, wt4[r].z, a);
                    a = fmaf(x4[r].w, wt4[r].w, a);
                    acct[r] = a;
                }
            }
            #pragma unroll
            for (int r = 0; r < RPW; r++) x4[r] = x4n[r];
        }

        // warp butterfly reduction over lanes (disjoint H slices)
        #pragma unroll
        for (int off = 16; off > 0; off >>= 1) {
            #pragma unroll
            for (int r = 0; r < RPW; r++) {
                if (HT) acct[r] += __shfl_xor_sync(0xffffffffu, acct[r], off);
                #pragma unroll
                for (int j = 0; j < NC; j++)
                    acc[r][j] += __shfl_xor_sync(0xffffffffu, acc[r][j], off);
            }
        }

        // outputs
        #pragma unroll
        for (int r = 0; r < RPW; r++) {
            const int n = row0 + r;
            float* pmn_row = out + (size_t)2 * NN + (size_t)n * KN + kbase;
            #pragma unroll
            for (int j = 0; j < NC; j++) {
                if (lane == j) pmn_row[j] = expf(acc[r][j] + s_nb[j]);
            }
            if (HT && lane == NC) {
                out[n] = expf(acct[r] + bias[tgt[r]]);
            }
        }
    }
}

__global__ __launch_bounds__(NTHREADS, 3)
void nce_kernel(const float* __restrict__ input,
                const float* __restrict__ weight,
                const float* __restrict__ bias,
                const float* __restrict__ unig,
                const int* __restrict__ target,
                const int* __restrict__ noise,
                float* __restrict__ out)
{
    extern __shared__ __align__(16) float sw[];   // up to 7 x 2048 noise rows
    __shared__ float s_nb[MAXNC];
    __shared__ float s_nu[KN];
    __shared__ int   s_nk[MAXNC];

    const int tid   = threadIdx.x;
    const int lane  = tid & 31;
    const int wid   = tid >> 5;
    const int bid   = blockIdx.x;
    const int q     = bid & (NQ - 1);
    const int rb    = (bid >> 2) * RPB;
    const int kbase = c_kbase[q];
    const int nc    = c_kcnt[q];

    if (tid < nc) {
        int nk = noise[kbase + tid];
        s_nk[tid] = nk;
        s_nb[tid] = bias[nk];
    }
    if (q == 0 && tid < KN) s_nu[tid] = unig[noise[tid]];
    __syncthreads();

    // ---- early independent outputs (quarter 0 only): pnn + pnt ----
    if (q == 0) {
        const size_t pnn_base = (size_t)2 * NN + (size_t)NN * KN + (size_t)rb * KN;
        #pragma unroll 1
        for (int i = tid; i < RPB * KN; i += NTHREADS)
            out[pnn_base + i] = s_nu[i % KN];
        if (tid < RPB) {
            int n = rb + tid;
            out[NN + n] = unig[target[n]];
        }
    }

    // ---- fill this quarter's noise tile into smem (coalesced, once) ----
    {
        const float4* w4 = reinterpret_cast<const float4*>(weight);
        float4* s4 = reinterpret_cast<float4*>(sw);
        const int total = nc * H4;
        #pragma unroll 1
        for (int idx = tid; idx < total; idx += NTHREADS) {
            int j = idx >> 9;          // / H4
            int h = idx & (H4 - 1);
            s4[idx] = w4[(size_t)s_nk[j] * H4 + h];
        }
    }
    __syncthreads();
    // ======== free-running from here ========

    switch (q) {
        case 0: run_quarter<7, false>(input, weight, bias, target, sw, s_nb, out, rb, wid, lane, 0);  break;
        case 1: run_quarter<7, false>(input, weight, bias, target, sw, s_nb, out, rb, wid, lane, 7);  break;
        case 2: run_quarter<6, false>(input, weight, bias, target, sw, s_nb, out, rb, wid, lane, 14); break;
        default: run_quarter<5, true>(input, weight, bias, target, sw, s_nb, out, rb, wid, lane, 20); break;
    }
}

extern "C" void kernel_launch(void* const* d_in, const int* in_sizes, int n_in,
                              void* d_out, int out_size) {
    const float* input  = (const float*)d_in[0];
    const float* weight = (const float*)d_in[1];
    const float* bias   = (const float*)d_in[2];
    const float* unig   = (const float*)d_in[3];
    const int*   target = (const int*)d_in[4];
    const int*   noise  = (const int*)d_in[5];
    float* out = (float*)d_out;

    cudaFuncSetAttribute(nce_kernel,
                         cudaFuncAttributeMaxDynamicSharedMemorySize, SMEM_BYTES);
    nce_kernel<<<NROWBLK * NQ, NTHREADS, SMEM_BYTES>>>(input, weight, bias, unig,
                                                       target, noise, out);
}